// round 16
// baseline (speedup 1.0000x reference)
#include <cuda_runtime.h>
#include <cuda_bf16.h>
#include <cuda_fp16.h>
#include <cstdint>

#define N_NODES 50000
#define E_EDGES 400000
#define DIN     256
#define HF      256
#define NH      4
#define FD      64
#define NP      3
#define HID     128
#define NEG     0.2f
#define NPN     (NP * N_NODES)

// ================= scratch =================
__device__ __align__(16) float g_z [(size_t)NP * N_NODES * HF];
__device__ __align__(16) float g_as[NPN * NH];
__device__ __align__(16) float g_ad[NPN * NH];
__device__ __align__(16) float g_s [NPN * NH];
__device__ int   g_cnt[NPN];
__device__ int   g_off[NPN];
__device__ int   g_cur[NPN];
__device__ int   g_srcs[(size_t)NP * E_EDGES];
__device__ float g_wsum[NP];
__device__ __align__(16) __half g_h2f[(size_t)N_NODES * 512];         // h [hi|lo] fp16
__device__ __align__(16) __half g_wtf[(size_t)NP * HF * DIN];         // W^T fp16 [p][n][k]
__device__ __align__(16) __nv_bfloat16 g_w1t[(size_t)HID * HF];       // w1^T bf16
__device__ __align__(16) __half        g_xwh[(size_t)NP * N_NODES * HF];  // xw fp16
__device__ __align__(16) __nv_bfloat16 g_zb [(size_t)NPN * HF];       // z bf16

__device__ __forceinline__ float lrelu(float x) { return x > 0.f ? x : NEG * x; }
__device__ __forceinline__ float tanh_fast(float x) {
    float y; asm("tanh.approx.f32 %0, %1;" : "=f"(y) : "f"(x)); return y;
}
__device__ __forceinline__ uint32_t smem_u32(const void* p) {
    uint32_t a;
    asm("{ .reg .u64 t; cvta.to.shared.u64 t, %1; cvt.u32.u64 %0, t; }" : "=r"(a) : "l"(p));
    return a;
}
#define SWZ128(o) ((o) ^ (((o) >> 3) & 0x70))
#define CP_ASYNC16(sm, gm) \
    asm volatile("cp.async.cg.shared.global [%0], [%1], 16;" :: "r"(sm), "l"(gm) : "memory")
#define CP_COMMIT()   asm volatile("cp.async.commit_group;" ::: "memory")
#define CP_WAIT(N)    asm volatile("cp.async.wait_group %0;" :: "n"(N) : "memory")

__device__ __forceinline__ void ldsm_x4(uint32_t& r0, uint32_t& r1, uint32_t& r2, uint32_t& r3,
                                        uint32_t addr) {
    asm volatile("ldmatrix.sync.aligned.m8n8.x4.shared.b16 {%0,%1,%2,%3}, [%4];"
                 : "=r"(r0), "=r"(r1), "=r"(r2), "=r"(r3) : "r"(addr));
}
__device__ __forceinline__ void mma_f16(float* c, const uint32_t* a, uint32_t b0, uint32_t b1) {
    asm volatile("mma.sync.aligned.m16n8k16.row.col.f32.f16.f16.f32 "
                 "{%0,%1,%2,%3}, {%4,%5,%6,%7}, {%8,%9}, {%0,%1,%2,%3};"
                 : "+f"(c[0]), "+f"(c[1]), "+f"(c[2]), "+f"(c[3])
                 : "r"(a[0]), "r"(a[1]), "r"(a[2]), "r"(a[3]), "r"(b0), "r"(b1));
}
__device__ __forceinline__ void mma_bf16(float* c, const uint32_t* a, uint32_t b0, uint32_t b1) {
    asm volatile("mma.sync.aligned.m16n8k16.row.col.f32.bf16.bf16.f32 "
                 "{%0,%1,%2,%3}, {%4,%5,%6,%7}, {%8,%9}, {%0,%1,%2,%3};"
                 : "+f"(c[0]), "+f"(c[1]), "+f"(c[2]), "+f"(c[3])
                 : "r"(a[0]), "r"(a[1]), "r"(a[2]), "r"(a[3]), "r"(b0), "r"(b1));
}

// ================= CSR setup =================
__global__ void hist_k(const int* __restrict__ e0, const int* __restrict__ e1,
                       const int* __restrict__ e2) {
    int idx = blockIdx.x * blockDim.x + threadIdx.x;
    if (idx >= NP * E_EDGES) return;
    int p = idx / E_EDGES, e = idx - p * E_EDGES;
    const int* ei = (p == 0) ? e0 : (p == 1) ? e1 : e2;
    atomicAdd(&g_cnt[p * N_NODES + ei[E_EDGES + e]], 1);
}
__global__ __launch_bounds__(1024) void scan_k() {
    __shared__ int sums[1024];
    const int t = threadIdx.x;
    const int chunk = (NPN + 1023) / 1024;
    int b = t * chunk, e = min(b + chunk, NPN);
    int s = 0;
    for (int i = b; i < e; i++) s += g_cnt[i];
    sums[t] = s;
    __syncthreads();
    for (int o = 1; o < 1024; o <<= 1) {
        int v = (t >= o) ? sums[t - o] : 0;
        __syncthreads();
        sums[t] += v;
        __syncthreads();
    }
    int run = (t == 0) ? 0 : sums[t - 1];
    for (int i = b; i < e; i++) {
        int c = g_cnt[i];
        g_off[i] = run; g_cur[i] = run; run += c;
    }
}
__global__ void scatter_k(const int* __restrict__ e0, const int* __restrict__ e1,
                          const int* __restrict__ e2) {
    int idx = blockIdx.x * blockDim.x + threadIdx.x;
    if (idx >= NP * E_EDGES) return;
    int p = idx / E_EDGES, e = idx - p * E_EDGES;
    const int* ei = (p == 0) ? e0 : (p == 1) ? e1 : e2;
    int pos = atomicAdd(&g_cur[p * N_NODES + ei[E_EDGES + e]], 1);
    g_srcs[pos] = ei[e];
}

// ================= conversions =================
__global__ void conv_h_k(const float* __restrict__ h) {
    int i = blockIdx.x * blockDim.x + threadIdx.x;
    if (i >= N_NODES * DIN) return;
    int row = i >> 8, k = i & 255;
    float f = h[i];
    __half hi = __float2half(f);
    size_t base = (size_t)row * 512 + k;
    g_h2f[base] = hi;
    g_h2f[base + 256] = __float2half(f - __half2float(hi));
}
// tiled transpose: z<3 -> W[p][k][n] -> g_wtf[p][n][k]; z==3 -> w1[k][n] -> g_w1t[n][k]
__global__ __launch_bounds__(1024) void transpose_k(const float* __restrict__ W,
                                                    const float* __restrict__ w1) {
    __shared__ float t[32][33];
    const int p = blockIdx.z;
    const int tx = threadIdx.x, ty = threadIdx.y;
    if (p < NP) {
        int k = blockIdx.y * 32 + ty;
        int n = blockIdx.x * 32 + tx;
        t[ty][tx] = W[p * 65536 + k * 256 + n];
        __syncthreads();
        int nn = blockIdx.x * 32 + ty;
        int kk = blockIdx.y * 32 + tx;
        g_wtf[(size_t)p * 65536 + nn * 256 + kk] = __float2half(t[tx][ty]);
    } else {
        if (blockIdx.x >= 4) return;   // w1 n-dim = 128
        int k = blockIdx.y * 32 + ty;
        int n = blockIdx.x * 32 + tx;
        t[ty][tx] = w1[k * HID + n];
        __syncthreads();
        int nn = blockIdx.x * 32 + ty;
        int kk = blockIdx.y * 32 + tx;
        g_w1t[(size_t)nn * 256 + kk] = __float2bfloat16(t[tx][ty]);
    }
}

// ================= feature GEMM 128x256 (512 thr), fp16 [hi|lo], fused alpha =====
#define GSMEM 100352
__global__ __launch_bounds__(512) void gemm_mma_k(const float* __restrict__ att_src,
                                                  const float* __restrict__ att_dst) {
    extern __shared__ char smem[];
    const int tid = threadIdx.x;
    const int wid = tid >> 5, lane = tid & 31;
    const int wm = wid & 3, wn = wid >> 2;     // wn = head
    const int row0 = blockIdx.x * 128;
    const int p = blockIdx.z;

    float* attS = (float*)(smem + 98304);
    float* attD = (float*)(smem + 99328);
    if (tid < 256) {
        attS[tid] = att_src[p * 256 + tid];
        attD[tid] = att_dst[p * 256 + tid];
    }

    const char* Ag = (const char*)g_h2f;
    const char* Bg = (const char*)(g_wtf + (size_t)p * HF * DIN);

    float c[2][8][4];
    #pragma unroll
    for (int a = 0; a < 2; a++)
        #pragma unroll
        for (int b = 0; b < 8; b++)
            #pragma unroll
            for (int q = 0; q < 4; q++) c[a][b][q] = 0.f;

    const uint32_t sm0 = smem_u32(smem);

    auto load_tile = [&](int kc, int buf) {
        const int ka_off = kc * 128;
        const int kb_off = (kc & 3) * 128;
        #pragma unroll
        for (int u = 0; u < 2; u++) {
            int i = tid + u * 512;
            int r = i >> 3, q = i & 7;
            uint32_t so = SWZ128((uint32_t)(r * 128 + q * 16));
            int gr = row0 + r;
            uint32_t sa = sm0 + buf * 16384 + so;
            if (gr < N_NODES)
                CP_ASYNC16(sa, Ag + (size_t)gr * 1024 + ka_off + q * 16);
            else
                *(uint4*)(smem + buf * 16384 + so) = make_uint4(0u, 0u, 0u, 0u);
        }
        #pragma unroll
        for (int u = 0; u < 4; u++) {
            int i = tid + u * 512;
            int r = i >> 3, q = i & 7;
            uint32_t so = SWZ128((uint32_t)(r * 128 + q * 16));
            CP_ASYNC16(sm0 + 32768 + buf * 32768 + so,
                       Bg + (size_t)r * 512 + kb_off + q * 16);
        }
    };

    load_tile(0, 0);
    CP_COMMIT();

    for (int kc = 0; kc < 8; kc++) {
        const int cur = kc & 1;
        if (kc + 1 < 8) {
            load_tile(kc + 1, cur ^ 1);
            CP_COMMIT();
            CP_WAIT(1);
        } else {
            CP_WAIT(0);
        }
        __syncthreads();
        const uint32_t sAb = sm0 + cur * 16384;
        const uint32_t sBb = sm0 + 32768 + cur * 32768;
        #pragma unroll
        for (int ks = 0; ks < 4; ks++) {
            const int k0 = ks * 16;
            uint32_t a[2][4], b[4][4];
            #pragma unroll
            for (int fm = 0; fm < 2; fm++) {
                int row = wm * 32 + fm * 16 + ((lane >> 3) & 1) * 8 + (lane & 7);
                int kcol = k0 + (lane >> 4) * 8;
                ldsm_x4(a[fm][0], a[fm][1], a[fm][2], a[fm][3],
                        sAb + SWZ128((uint32_t)(row * 128 + kcol * 2)));
            }
            #pragma unroll
            for (int fp = 0; fp < 4; fp++) {
                int nrow = wn * 64 + fp * 16 + (lane >> 4) * 8 + (lane & 7);
                int kcol = k0 + ((lane >> 3) & 1) * 8;
                ldsm_x4(b[fp][0], b[fp][1], b[fp][2], b[fp][3],
                        sBb + SWZ128((uint32_t)(nrow * 128 + kcol * 2)));
            }
            #pragma unroll
            for (int fm = 0; fm < 2; fm++)
                #pragma unroll
                for (int fn = 0; fn < 8; fn++)
                    mma_f16(c[fm][fn], a[fm], b[fn >> 1][(fn & 1) * 2], b[fn >> 1][(fn & 1) * 2 + 1]);
        }
        __syncthreads();
    }

    float as0[8], as1[8], ad0[8], ad1[8];
    #pragma unroll
    for (int fn = 0; fn < 8; fn++) {
        int col = wn * 64 + fn * 8 + (lane & 3) * 2;
        as0[fn] = attS[col]; as1[fn] = attS[col + 1];
        ad0[fn] = attD[col]; ad1[fn] = attD[col + 1];
    }

    __half* outp = g_xwh + (size_t)p * N_NODES * HF;
    #pragma unroll
    for (int fm = 0; fm < 2; fm++) {
        #pragma unroll
        for (int half = 0; half < 2; half++) {
            int grow = row0 + wm * 32 + fm * 16 + (lane >> 2) + half * 8;
            float vs = 0.f, vd = 0.f;
            #pragma unroll
            for (int fn = 0; fn < 8; fn++) {
                float x0 = c[fm][fn][half * 2], x1 = c[fm][fn][half * 2 + 1];
                vs += x0 * as0[fn] + x1 * as1[fn];
                vd += x0 * ad0[fn] + x1 * ad1[fn];
            }
            vs += __shfl_xor_sync(0xffffffffu, vs, 1);
            vs += __shfl_xor_sync(0xffffffffu, vs, 2);
            vd += __shfl_xor_sync(0xffffffffu, vd, 1);
            vd += __shfl_xor_sync(0xffffffffu, vd, 2);
            if ((lane & 3) == 0 && grow < N_NODES) {
                size_t ng = (size_t)p * N_NODES + grow;
                g_as[ng * NH + wn] = vs;
                g_ad[ng * NH + wn] = vd;
                g_s [ng * NH + wn] = __expf(lrelu(vs + vd));
            }
            if (grow < N_NODES) {
                #pragma unroll
                for (int fn = 0; fn < 8; fn++) {
                    int col = wn * 64 + fn * 8 + (lane & 3) * 2;
                    __half2 hv = __floats2half2_rn(c[fm][fn][half * 2], c[fm][fn][half * 2 + 1]);
                    *(__half2*)(outp + (size_t)grow * HF + col) = hv;
                }
            }
        }
    }
}

// ================= edge-parallel denominators =================
__global__ void edge_sum_k(const int* __restrict__ e0, const int* __restrict__ e1,
                           const int* __restrict__ e2) {
    int idx = blockIdx.x * blockDim.x + threadIdx.x;
    if (idx >= NP * E_EDGES) return;
    int p = idx / E_EDGES, e = idx - p * E_EDGES;
    const int* ei = (p == 0) ? e0 : (p == 1) ? e1 : e2;
    int src = ei[e];
    int dst = ei[E_EDGES + e];
    size_t so = (size_t)p * N_NODES * NH + (size_t)src * NH;
    size_t dr = (size_t)p * N_NODES * NH + (size_t)dst * NH;
    float4 a = *(const float4*)&g_as[so];
    float4 d = *(const float4*)&g_ad[dr];
    atomicAdd(&g_s[dr + 0], __expf(lrelu(a.x + d.x)));
    atomicAdd(&g_s[dr + 1], __expf(lrelu(a.y + d.y)));
    atomicAdd(&g_s[dr + 2], __expf(lrelu(a.z + d.z)));
    atomicAdd(&g_s[dr + 3], __expf(lrelu(a.w + d.w)));
}

// ================= aggregation: warp per node, fp16 gather =================
__global__ __launch_bounds__(256) void agg_k(const float* __restrict__ bias_all) {
    const int wib = threadIdx.x >> 5;
    const int lane = threadIdx.x & 31;
    const int n = blockIdx.x * 8 + wib;
    const int p = blockIdx.y;
    if (n >= N_NODES) return;

    const size_t ng = (size_t)p * N_NODES + n;
    const int beg = g_off[ng];
    const int end = g_cur[ng];
    const int head = lane >> 3;
    const float ad = g_ad[ng * NH + head];
    const float inv = 1.f / g_s[ng * NH + head];
    const float asn = g_as[ng * NH + head];
    const float selfw = __expf(lrelu(asn + ad)) * inv;
    const float* asp = g_as + (size_t)p * N_NODES * NH;
    const __half* xwp = g_xwh + (size_t)p * N_NODES * HF;

    const int c = lane * 8;
    float acc[8];
    {
        uint4 hv = *(const uint4*)(xwp + (size_t)n * HF + c);
        const __half2* h2 = (const __half2*)&hv;
        #pragma unroll
        for (int i = 0; i < 4; i++) {
            float2 f = __half22float2(h2[i]);
            acc[i * 2] = selfw * f.x;
            acc[i * 2 + 1] = selfw * f.y;
        }
    }

    int j = beg;
    for (; j + 2 <= end; j += 2) {
        int s0 = g_srcs[j], s1 = g_srcs[j + 1];
        uint4 v0 = *(const uint4*)(xwp + (size_t)s0 * HF + c);
        uint4 v1 = *(const uint4*)(xwp + (size_t)s1 * HF + c);
        float w0 = __expf(lrelu(asp[s0 * NH + head] + ad)) * inv;
        float w1 = __expf(lrelu(asp[s1 * NH + head] + ad)) * inv;
        const __half2* h0 = (const __half2*)&v0;
        const __half2* h1 = (const __half2*)&v1;
        #pragma unroll
        for (int i = 0; i < 4; i++) {
            float2 f0 = __half22float2(h0[i]);
            float2 f1 = __half22float2(h1[i]);
            acc[i * 2]     += w0 * f0.x + w1 * f1.x;
            acc[i * 2 + 1] += w0 * f0.y + w1 * f1.y;
        }
    }
    if (j < end) {
        int s0 = g_srcs[j];
        uint4 v0 = *(const uint4*)(xwp + (size_t)s0 * HF + c);
        float w0 = __expf(lrelu(asp[s0 * NH + head] + ad)) * inv;
        const __half2* h0 = (const __half2*)&v0;
        #pragma unroll
        for (int i = 0; i < 4; i++) {
            float2 f0 = __half22float2(h0[i]);
            acc[i * 2]     += w0 * f0.x;
            acc[i * 2 + 1] += w0 * f0.y;
        }
    }

    const float* bp = bias_all + p * HF + c;
    #pragma unroll
    for (int i = 0; i < 8; i++) acc[i] += bp[i];

    float* zp = g_z + ng * HF + c;
    *(float4*)zp       = make_float4(acc[0], acc[1], acc[2], acc[3]);
    *(float4*)(zp + 4) = make_float4(acc[4], acc[5], acc[6], acc[7]);

    uint4 pk;
    __nv_bfloat162 b01 = __floats2bfloat162_rn(acc[0], acc[1]);
    __nv_bfloat162 b23 = __floats2bfloat162_rn(acc[2], acc[3]);
    __nv_bfloat162 b45 = __floats2bfloat162_rn(acc[4], acc[5]);
    __nv_bfloat162 b67 = __floats2bfloat162_rn(acc[6], acc[7]);
    pk.x = *(uint32_t*)&b01; pk.y = *(uint32_t*)&b23;
    pk.z = *(uint32_t*)&b45; pk.w = *(uint32_t*)&b67;
    *(uint4*)(g_zb + ng * HF + c) = pk;
}

// ================= semantic GEMM (bf16, cp.async, tanh.approx) ===================
__global__ __launch_bounds__(256) void sem_mma_k(const float* __restrict__ b1,
                                                 const float* __restrict__ w2) {
    __shared__ __align__(16) char sA[2][16384];
    __shared__ __align__(16) char sB[2][16384];
    __shared__ float s_b1[HID], s_w2[HID], s_acc[NP];
    const int tid = threadIdx.x;
    const int wid = tid >> 5, lane = tid & 31;
    const int wm = wid & 3, wn = wid >> 2;
    const int row0 = blockIdx.x * 128;

    if (tid < NP) s_acc[tid] = 0.f;
    if (tid < HID) { s_b1[tid] = b1[tid]; s_w2[tid] = w2[tid]; }

    const char* Ag = (const char*)g_zb;
    const char* Bg = (const char*)g_w1t;

    float c[2][8][4];
    #pragma unroll
    for (int a = 0; a < 2; a++)
        #pragma unroll
        for (int b = 0; b < 8; b++)
            #pragma unroll
            for (int q = 0; q < 4; q++) c[a][b][q] = 0.f;

    const uint32_t sAb0 = smem_u32(sA[0]), sBb0 = smem_u32(sB[0]);

    auto load_tile = [&](int kc, int buf) {
        #pragma unroll
        for (int u = 0; u < 4; u++) {
            int i = tid + u * 256;
            int r = i >> 3, q = i & 7;
            uint32_t so = SWZ128((uint32_t)(r * 128 + q * 16));
            int gr = row0 + r;
            uint32_t sa = sAb0 + buf * 16384 + so;
            if (gr < NPN)
                CP_ASYNC16(sa, Ag + (size_t)gr * 512 + kc * 128 + q * 16);
            else
                *(uint4*)(sA[buf] + so) = make_uint4(0u, 0u, 0u, 0u);
            CP_ASYNC16(sBb0 + buf * 16384 + so, Bg + (size_t)r * 512 + kc * 128 + q * 16);
        }
    };

    load_tile(0, 0);
    CP_COMMIT();

    for (int kc = 0; kc < 4; kc++) {
        const int cur = kc & 1;
        if (kc + 1 < 4) {
            load_tile(kc + 1, cur ^ 1);
            CP_COMMIT();
            CP_WAIT(1);
        } else {
            CP_WAIT(0);
        }
        __syncthreads();
        const uint32_t sAb = sAb0 + cur * 16384;
        const uint32_t sBb = sBb0 + cur * 16384;
        #pragma unroll
        for (int ks = 0; ks < 4; ks++) {
            const int k0 = ks * 16;
            uint32_t a[2][4], b[4][4];
            #pragma unroll
            for (int fm = 0; fm < 2; fm++) {
                int row = wm * 32 + fm * 16 + ((lane >> 3) & 1) * 8 + (lane & 7);
                int kcol = k0 + (lane >> 4) * 8;
                ldsm_x4(a[fm][0], a[fm][1], a[fm][2], a[fm][3],
                        sAb + SWZ128((uint32_t)(row * 128 + kcol * 2)));
            }
            #pragma unroll
            for (int fp = 0; fp < 4; fp++) {
                int nrow = wn * 64 + fp * 16 + (lane >> 4) * 8 + (lane & 7);
                int kcol = k0 + ((lane >> 3) & 1) * 8;
                ldsm_x4(b[fp][0], b[fp][1], b[fp][2], b[fp][3],
                        sBb + SWZ128((uint32_t)(nrow * 128 + kcol * 2)));
            }
            #pragma unroll
            for (int fm = 0; fm < 2; fm++)
                #pragma unroll
                for (int fn = 0; fn < 8; fn++)
                    mma_bf16(c[fm][fn], a[fm], b[fn >> 1][(fn & 1) * 2], b[fn >> 1][(fn & 1) * 2 + 1]);
        }
        __syncthreads();
    }

    #pragma unroll
    for (int fm = 0; fm < 2; fm++) {
        int rbase = row0 + wm * 32 + fm * 16 + (lane >> 2);
        #pragma unroll
        for (int half = 0; half < 2; half++) {
            int grow = rbase + half * 8;
            float v = 0.f;
            #pragma unroll
            for (int fn = 0; fn < 8; fn++) {
                int col = wn * 64 + fn * 8 + (lane & 3) * 2;
                v += tanh_fast(c[fm][fn][half * 2]     + s_b1[col])     * s_w2[col];
                v += tanh_fast(c[fm][fn][half * 2 + 1] + s_b1[col + 1]) * s_w2[col + 1];
            }
            v += __shfl_xor_sync(0xffffffffu, v, 1);
            v += __shfl_xor_sync(0xffffffffu, v, 2);
            if ((lane & 3) == 0 && grow < NPN)
                atomicAdd(&s_acc[grow / N_NODES], v);
        }
    }
    __syncthreads();
    if (tid < NP) atomicAdd(&g_wsum[tid], s_acc[tid]);
}

// ================= final combine =================
__global__ void final_k(float* __restrict__ out) {
    int idx = blockIdx.x * blockDim.x + threadIdx.x;
    if (idx >= N_NODES * (HF / 4)) return;
    float m0 = g_wsum[0] * (1.f / N_NODES);
    float m1 = g_wsum[1] * (1.f / N_NODES);
    float m2 = g_wsum[2] * (1.f / N_NODES);
    float mm = fmaxf(m0, fmaxf(m1, m2));
    float e0 = __expf(m0 - mm), e1 = __expf(m1 - mm), e2 = __expf(m2 - mm);
    float inv = 1.f / (e0 + e1 + e2);
    float b0 = e0 * inv, b1 = e1 * inv, b2 = e2 * inv;
    size_t off = (size_t)idx * 4;
    float4 z0 = *(const float4*)(g_z + off);
    float4 z1 = *(const float4*)(g_z + (size_t)N_NODES * HF + off);
    float4 z2 = *(const float4*)(g_z + (size_t)2 * N_NODES * HF + off);
    float4 o;
    o.x = b0 * z0.x + b1 * z1.x + b2 * z2.x;
    o.y = b0 * z0.y + b1 * z1.y + b2 * z2.y;
    o.z = b0 * z0.z + b1 * z1.z + b2 * z2.z;
    o.w = b0 * z0.w + b1 * z1.w + b2 * z2.w;
    *(float4*)(out + off) = o;
}

// ================= launch =================
extern "C" void kernel_launch(void* const* d_in, const int* in_sizes, int n_in,
                              void* d_out, int out_size) {
    const float* h        = (const float*)d_in[0];
    const int* e0         = (const int*)d_in[1];
    const int* e1         = (const int*)d_in[2];
    const int* e2         = (const int*)d_in[3];
    const float* gat_W    = (const float*)d_in[4];
    const float* att_src  = (const float*)d_in[5];
    const float* att_dst  = (const float*)d_in[6];
    const float* gat_bias = (const float*)d_in[7];
    const float* sa_w1    = (const float*)d_in[8];
    const float* sa_b1    = (const float*)d_in[9];
    const float* sa_w2    = (const float*)d_in[10];
    float* out = (float*)d_out;

    static bool init_done = false;
    static void* cnt_ptr = nullptr;
    static void* wsum_ptr = nullptr;
    static cudaStream_t s2 = nullptr;
    static cudaEvent_t evF = nullptr, evJ = nullptr;
    if (!init_done) {
        cudaFuncSetAttribute(gemm_mma_k, cudaFuncAttributeMaxDynamicSharedMemorySize, GSMEM);
        cudaGetSymbolAddress(&cnt_ptr, g_cnt);
        cudaGetSymbolAddress(&wsum_ptr, g_wsum);
        cudaStreamCreateWithFlags(&s2, cudaStreamNonBlocking);
        cudaEventCreateWithFlags(&evF, cudaEventDisableTiming);
        cudaEventCreateWithFlags(&evJ, cudaEventDisableTiming);
        init_done = true;
    }

    // fork: CSR setup on s2, concurrent with conv + GEMM chain on default stream
    cudaEventRecord(evF, 0);
    cudaStreamWaitEvent(s2, evF, 0);
    cudaMemsetAsync(cnt_ptr, 0, NPN * sizeof(int), s2);
    hist_k<<<(NP * E_EDGES + 255) / 256, 256, 0, s2>>>(e0, e1, e2);
    scan_k<<<1, 1024, 0, s2>>>();
    scatter_k<<<(NP * E_EDGES + 255) / 256, 256, 0, s2>>>(e0, e1, e2);
    cudaEventRecord(evJ, s2);

    // main chain
    cudaMemsetAsync(wsum_ptr, 0, NP * sizeof(float));
    conv_h_k<<<(N_NODES * DIN + 255) / 256, 256>>>(h);
    dim3 tgrid(8, 8, NP + 1);
    transpose_k<<<tgrid, dim3(32, 32)>>>(gat_W, sa_w1);

    dim3 ggrid((N_NODES + 127) / 128, 1, NP);
    gemm_mma_k<<<ggrid, 512, GSMEM>>>(att_src, att_dst);

    edge_sum_k<<<(NP * E_EDGES + 255) / 256, 256>>>(e0, e1, e2);

    // join: agg needs CSR
    cudaStreamWaitEvent(0, evJ, 0);

    dim3 agrid((N_NODES + 7) / 8, NP);
    agg_k<<<agrid, 256>>>(gat_bias);

    sem_mma_k<<<(NPN + 127) / 128, 256>>>(sa_b1, sa_w2);

    final_k<<<(N_NODES * (HF / 4) + 255) / 256, 256>>>(out);
}

// round 17
// speedup vs baseline: 1.0030x; 1.0030x over previous
#include <cuda_runtime.h>
#include <cuda_bf16.h>
#include <cuda_fp16.h>
#include <cstdint>

#define N_NODES 50000
#define E_EDGES 400000
#define DIN     256
#define HF      256
#define NH      4
#define FD      64
#define NP      3
#define HID     128
#define NEG     0.2f
#define NPN     (NP * N_NODES)

// ================= scratch =================
__device__ __align__(16) float g_z [(size_t)NP * N_NODES * HF];
__device__ __align__(16) float g_as[NPN * NH];
__device__ __align__(16) float g_ad[NPN * NH];
__device__ __align__(16) float g_s [NPN * NH];
__device__ int   g_cnt[NPN];
__device__ int   g_off[NPN];
__device__ int   g_cur[NPN];
__device__ int   g_srcs[(size_t)NP * E_EDGES];
__device__ float g_wsum[NP];
__device__ __align__(16) __half g_h2f[(size_t)N_NODES * 512];         // h [hi|lo] fp16
__device__ __align__(16) __half g_wtf[(size_t)NP * HF * DIN];         // W^T fp16 [p][n][k]
__device__ __align__(16) __nv_bfloat16 g_w1t[(size_t)HID * HF];       // w1^T bf16
__device__ __align__(16) __half        g_xwh[(size_t)NP * N_NODES * HF];  // xw fp16
__device__ __align__(16) __nv_bfloat16 g_zb [(size_t)NPN * HF];       // z bf16

__device__ __forceinline__ float lrelu(float x) { return x > 0.f ? x : NEG * x; }
__device__ __forceinline__ float tanh_fast(float x) {
    float y; asm("tanh.approx.f32 %0, %1;" : "=f"(y) : "f"(x)); return y;
}
__device__ __forceinline__ uint32_t smem_u32(const void* p) {
    uint32_t a;
    asm("{ .reg .u64 t; cvta.to.shared.u64 t, %1; cvt.u32.u64 %0, t; }" : "=r"(a) : "l"(p));
    return a;
}
#define SWZ128(o) ((o) ^ (((o) >> 3) & 0x70))
#define CP_ASYNC16(sm, gm) \
    asm volatile("cp.async.cg.shared.global [%0], [%1], 16;" :: "r"(sm), "l"(gm) : "memory")
#define CP_COMMIT()   asm volatile("cp.async.commit_group;" ::: "memory")
#define CP_WAIT(N)    asm volatile("cp.async.wait_group %0;" :: "n"(N) : "memory")

__device__ __forceinline__ void ldsm_x4(uint32_t& r0, uint32_t& r1, uint32_t& r2, uint32_t& r3,
                                        uint32_t addr) {
    asm volatile("ldmatrix.sync.aligned.m8n8.x4.shared.b16 {%0,%1,%2,%3}, [%4];"
                 : "=r"(r0), "=r"(r1), "=r"(r2), "=r"(r3) : "r"(addr));
}
__device__ __forceinline__ void mma_f16(float* c, const uint32_t* a, uint32_t b0, uint32_t b1) {
    asm volatile("mma.sync.aligned.m16n8k16.row.col.f32.f16.f16.f32 "
                 "{%0,%1,%2,%3}, {%4,%5,%6,%7}, {%8,%9}, {%0,%1,%2,%3};"
                 : "+f"(c[0]), "+f"(c[1]), "+f"(c[2]), "+f"(c[3])
                 : "r"(a[0]), "r"(a[1]), "r"(a[2]), "r"(a[3]), "r"(b0), "r"(b1));
}
__device__ __forceinline__ void mma_bf16(float* c, const uint32_t* a, uint32_t b0, uint32_t b1) {
    asm volatile("mma.sync.aligned.m16n8k16.row.col.f32.bf16.bf16.f32 "
                 "{%0,%1,%2,%3}, {%4,%5,%6,%7}, {%8,%9}, {%0,%1,%2,%3};"
                 : "+f"(c[0]), "+f"(c[1]), "+f"(c[2]), "+f"(c[3])
                 : "r"(a[0]), "r"(a[1]), "r"(a[2]), "r"(a[3]), "r"(b0), "r"(b1));
}

// ================= CSR setup =================
__global__ void hist_k(const int* __restrict__ e0, const int* __restrict__ e1,
                       const int* __restrict__ e2) {
    int idx = blockIdx.x * blockDim.x + threadIdx.x;
    if (idx >= NP * E_EDGES) return;
    int p = idx / E_EDGES, e = idx - p * E_EDGES;
    const int* ei = (p == 0) ? e0 : (p == 1) ? e1 : e2;
    atomicAdd(&g_cnt[p * N_NODES + ei[E_EDGES + e]], 1);
}
__global__ __launch_bounds__(1024) void scan_k() {
    __shared__ int sums[1024];
    const int t = threadIdx.x;
    const int chunk = (NPN + 1023) / 1024;
    int b = t * chunk, e = min(b + chunk, NPN);
    int s = 0;
    for (int i = b; i < e; i++) s += g_cnt[i];
    sums[t] = s;
    __syncthreads();
    for (int o = 1; o < 1024; o <<= 1) {
        int v = (t >= o) ? sums[t - o] : 0;
        __syncthreads();
        sums[t] += v;
        __syncthreads();
    }
    int run = (t == 0) ? 0 : sums[t - 1];
    for (int i = b; i < e; i++) {
        int c = g_cnt[i];
        g_off[i] = run; g_cur[i] = run; run += c;
    }
}
__global__ void scatter_k(const int* __restrict__ e0, const int* __restrict__ e1,
                          const int* __restrict__ e2) {
    int idx = blockIdx.x * blockDim.x + threadIdx.x;
    if (idx >= NP * E_EDGES) return;
    int p = idx / E_EDGES, e = idx - p * E_EDGES;
    const int* ei = (p == 0) ? e0 : (p == 1) ? e1 : e2;
    int pos = atomicAdd(&g_cur[p * N_NODES + ei[E_EDGES + e]], 1);
    g_srcs[pos] = ei[e];
}

// ================= conversions =================
__global__ void conv_h_k(const float* __restrict__ h) {
    int i = blockIdx.x * blockDim.x + threadIdx.x;
    if (i >= N_NODES * DIN) return;
    int row = i >> 8, k = i & 255;
    float f = h[i];
    __half hi = __float2half(f);
    size_t base = (size_t)row * 512 + k;
    g_h2f[base] = hi;
    g_h2f[base + 256] = __float2half(f - __half2float(hi));
}
// tiled transpose: z<3 -> W[p][k][n] -> g_wtf[p][n][k]; z==3 -> w1[k][n] -> g_w1t[n][k]
__global__ __launch_bounds__(1024) void transpose_k(const float* __restrict__ W,
                                                    const float* __restrict__ w1) {
    __shared__ float t[32][33];
    const int p = blockIdx.z;
    const int tx = threadIdx.x, ty = threadIdx.y;
    if (p < NP) {
        int k = blockIdx.y * 32 + ty;
        int n = blockIdx.x * 32 + tx;
        t[ty][tx] = W[p * 65536 + k * 256 + n];
        __syncthreads();
        int nn = blockIdx.x * 32 + ty;
        int kk = blockIdx.y * 32 + tx;
        g_wtf[(size_t)p * 65536 + nn * 256 + kk] = __float2half(t[tx][ty]);
    } else {
        if (blockIdx.x >= 4) return;   // w1 n-dim = 128
        int k = blockIdx.y * 32 + ty;
        int n = blockIdx.x * 32 + tx;
        t[ty][tx] = w1[k * HID + n];
        __syncthreads();
        int nn = blockIdx.x * 32 + ty;
        int kk = blockIdx.y * 32 + tx;
        g_w1t[(size_t)nn * 256 + kk] = __float2bfloat16(t[tx][ty]);
    }
}

// ================= feature GEMM 128x256 (512 thr), fp16 [hi|lo], fused alpha =====
#define GSMEM 100352
__global__ __launch_bounds__(512) void gemm_mma_k(const float* __restrict__ att_src,
                                                  const float* __restrict__ att_dst) {
    extern __shared__ char smem[];
    const int tid = threadIdx.x;
    const int wid = tid >> 5, lane = tid & 31;
    const int wm = wid & 3, wn = wid >> 2;     // wn = head
    const int row0 = blockIdx.x * 128;
    const int p = blockIdx.z;

    float* attS = (float*)(smem + 98304);
    float* attD = (float*)(smem + 99328);
    if (tid < 256) {
        attS[tid] = att_src[p * 256 + tid];
        attD[tid] = att_dst[p * 256 + tid];
    }

    const char* Ag = (const char*)g_h2f;
    const char* Bg = (const char*)(g_wtf + (size_t)p * HF * DIN);

    float c[2][8][4];
    #pragma unroll
    for (int a = 0; a < 2; a++)
        #pragma unroll
        for (int b = 0; b < 8; b++)
            #pragma unroll
            for (int q = 0; q < 4; q++) c[a][b][q] = 0.f;

    const uint32_t sm0 = smem_u32(smem);

    auto load_tile = [&](int kc, int buf) {
        const int ka_off = kc * 128;
        const int kb_off = (kc & 3) * 128;
        #pragma unroll
        for (int u = 0; u < 2; u++) {
            int i = tid + u * 512;
            int r = i >> 3, q = i & 7;
            uint32_t so = SWZ128((uint32_t)(r * 128 + q * 16));
            int gr = row0 + r;
            uint32_t sa = sm0 + buf * 16384 + so;
            if (gr < N_NODES)
                CP_ASYNC16(sa, Ag + (size_t)gr * 1024 + ka_off + q * 16);
            else
                *(uint4*)(smem + buf * 16384 + so) = make_uint4(0u, 0u, 0u, 0u);
        }
        #pragma unroll
        for (int u = 0; u < 4; u++) {
            int i = tid + u * 512;
            int r = i >> 3, q = i & 7;
            uint32_t so = SWZ128((uint32_t)(r * 128 + q * 16));
            CP_ASYNC16(sm0 + 32768 + buf * 32768 + so,
                       Bg + (size_t)r * 512 + kb_off + q * 16);
        }
    };

    load_tile(0, 0);
    CP_COMMIT();

    for (int kc = 0; kc < 8; kc++) {
        const int cur = kc & 1;
        if (kc + 1 < 8) {
            load_tile(kc + 1, cur ^ 1);
            CP_COMMIT();
            CP_WAIT(1);
        } else {
            CP_WAIT(0);
        }
        __syncthreads();
        const uint32_t sAb = sm0 + cur * 16384;
        const uint32_t sBb = sm0 + 32768 + cur * 32768;
        #pragma unroll
        for (int ks = 0; ks < 4; ks++) {
            const int k0 = ks * 16;
            uint32_t a[2][4], b[4][4];
            #pragma unroll
            for (int fm = 0; fm < 2; fm++) {
                int row = wm * 32 + fm * 16 + ((lane >> 3) & 1) * 8 + (lane & 7);
                int kcol = k0 + (lane >> 4) * 8;
                ldsm_x4(a[fm][0], a[fm][1], a[fm][2], a[fm][3],
                        sAb + SWZ128((uint32_t)(row * 128 + kcol * 2)));
            }
            #pragma unroll
            for (int fp = 0; fp < 4; fp++) {
                int nrow = wn * 64 + fp * 16 + (lane >> 4) * 8 + (lane & 7);
                int kcol = k0 + ((lane >> 3) & 1) * 8;
                ldsm_x4(b[fp][0], b[fp][1], b[fp][2], b[fp][3],
                        sBb + SWZ128((uint32_t)(nrow * 128 + kcol * 2)));
            }
            #pragma unroll
            for (int fm = 0; fm < 2; fm++)
                #pragma unroll
                for (int fn = 0; fn < 8; fn++)
                    mma_f16(c[fm][fn], a[fm], b[fn >> 1][(fn & 1) * 2], b[fn >> 1][(fn & 1) * 2 + 1]);
        }
        __syncthreads();
    }

    float as0[8], as1[8], ad0[8], ad1[8];
    #pragma unroll
    for (int fn = 0; fn < 8; fn++) {
        int col = wn * 64 + fn * 8 + (lane & 3) * 2;
        as0[fn] = attS[col]; as1[fn] = attS[col + 1];
        ad0[fn] = attD[col]; ad1[fn] = attD[col + 1];
    }

    __half* outp = g_xwh + (size_t)p * N_NODES * HF;
    #pragma unroll
    for (int fm = 0; fm < 2; fm++) {
        #pragma unroll
        for (int half = 0; half < 2; half++) {
            int grow = row0 + wm * 32 + fm * 16 + (lane >> 2) + half * 8;
            float vs = 0.f, vd = 0.f;
            #pragma unroll
            for (int fn = 0; fn < 8; fn++) {
                float x0 = c[fm][fn][half * 2], x1 = c[fm][fn][half * 2 + 1];
                vs += x0 * as0[fn] + x1 * as1[fn];
                vd += x0 * ad0[fn] + x1 * ad1[fn];
            }
            vs += __shfl_xor_sync(0xffffffffu, vs, 1);
            vs += __shfl_xor_sync(0xffffffffu, vs, 2);
            vd += __shfl_xor_sync(0xffffffffu, vd, 1);
            vd += __shfl_xor_sync(0xffffffffu, vd, 2);
            if ((lane & 3) == 0 && grow < N_NODES) {
                size_t ng = (size_t)p * N_NODES + grow;
                g_as[ng * NH + wn] = vs;
                g_ad[ng * NH + wn] = vd;
                g_s [ng * NH + wn] = __expf(lrelu(vs + vd));
            }
            if (grow < N_NODES) {
                #pragma unroll
                for (int fn = 0; fn < 8; fn++) {
                    int col = wn * 64 + fn * 8 + (lane & 3) * 2;
                    __half2 hv = __floats2half2_rn(c[fm][fn][half * 2], c[fm][fn][half * 2 + 1]);
                    *(__half2*)(outp + (size_t)grow * HF + col) = hv;
                }
            }
        }
    }
}

// ================= edge-parallel denominators =================
__global__ void edge_sum_k(const int* __restrict__ e0, const int* __restrict__ e1,
                           const int* __restrict__ e2) {
    int idx = blockIdx.x * blockDim.x + threadIdx.x;
    if (idx >= NP * E_EDGES) return;
    int p = idx / E_EDGES, e = idx - p * E_EDGES;
    const int* ei = (p == 0) ? e0 : (p == 1) ? e1 : e2;
    int src = ei[e];
    int dst = ei[E_EDGES + e];
    size_t so = (size_t)p * N_NODES * NH + (size_t)src * NH;
    size_t dr = (size_t)p * N_NODES * NH + (size_t)dst * NH;
    float4 a = *(const float4*)&g_as[so];
    float4 d = *(const float4*)&g_ad[dr];
    atomicAdd(&g_s[dr + 0], __expf(lrelu(a.x + d.x)));
    atomicAdd(&g_s[dr + 1], __expf(lrelu(a.y + d.y)));
    atomicAdd(&g_s[dr + 2], __expf(lrelu(a.z + d.z)));
    atomicAdd(&g_s[dr + 3], __expf(lrelu(a.w + d.w)));
}

// ================= aggregation: warp per node, fp16 gather =================
__global__ __launch_bounds__(256) void agg_k(const float* __restrict__ bias_all) {
    const int wib = threadIdx.x >> 5;
    const int lane = threadIdx.x & 31;
    const int n = blockIdx.x * 8 + wib;
    const int p = blockIdx.y;
    if (n >= N_NODES) return;

    const size_t ng = (size_t)p * N_NODES + n;
    const int beg = g_off[ng];
    const int end = g_cur[ng];
    const int head = lane >> 3;
    const float ad = g_ad[ng * NH + head];
    const float inv = 1.f / g_s[ng * NH + head];
    const float asn = g_as[ng * NH + head];
    const float selfw = __expf(lrelu(asn + ad)) * inv;
    const float* asp = g_as + (size_t)p * N_NODES * NH;
    const __half* xwp = g_xwh + (size_t)p * N_NODES * HF;

    const int c = lane * 8;
    float acc[8];
    {
        uint4 hv = *(const uint4*)(xwp + (size_t)n * HF + c);
        const __half2* h2 = (const __half2*)&hv;
        #pragma unroll
        for (int i = 0; i < 4; i++) {
            float2 f = __half22float2(h2[i]);
            acc[i * 2] = selfw * f.x;
            acc[i * 2 + 1] = selfw * f.y;
        }
    }

    int j = beg;
    for (; j + 2 <= end; j += 2) {
        int s0 = g_srcs[j], s1 = g_srcs[j + 1];
        uint4 v0 = *(const uint4*)(xwp + (size_t)s0 * HF + c);
        uint4 v1 = *(const uint4*)(xwp + (size_t)s1 * HF + c);
        float w0 = __expf(lrelu(asp[s0 * NH + head] + ad)) * inv;
        float w1 = __expf(lrelu(asp[s1 * NH + head] + ad)) * inv;
        const __half2* h0 = (const __half2*)&v0;
        const __half2* h1 = (const __half2*)&v1;
        #pragma unroll
        for (int i = 0; i < 4; i++) {
            float2 f0 = __half22float2(h0[i]);
            float2 f1 = __half22float2(h1[i]);
            acc[i * 2]     += w0 * f0.x + w1 * f1.x;
            acc[i * 2 + 1] += w0 * f0.y + w1 * f1.y;
        }
    }
    if (j < end) {
        int s0 = g_srcs[j];
        uint4 v0 = *(const uint4*)(xwp + (size_t)s0 * HF + c);
        float w0 = __expf(lrelu(asp[s0 * NH + head] + ad)) * inv;
        const __half2* h0 = (const __half2*)&v0;
        #pragma unroll
        for (int i = 0; i < 4; i++) {
            float2 f0 = __half22float2(h0[i]);
            acc[i * 2]     += w0 * f0.x;
            acc[i * 2 + 1] += w0 * f0.y;
        }
    }

    const float* bp = bias_all + p * HF + c;
    #pragma unroll
    for (int i = 0; i < 8; i++) acc[i] += bp[i];

    float* zp = g_z + ng * HF + c;
    *(float4*)zp       = make_float4(acc[0], acc[1], acc[2], acc[3]);
    *(float4*)(zp + 4) = make_float4(acc[4], acc[5], acc[6], acc[7]);

    uint4 pk;
    __nv_bfloat162 b01 = __floats2bfloat162_rn(acc[0], acc[1]);
    __nv_bfloat162 b23 = __floats2bfloat162_rn(acc[2], acc[3]);
    __nv_bfloat162 b45 = __floats2bfloat162_rn(acc[4], acc[5]);
    __nv_bfloat162 b67 = __floats2bfloat162_rn(acc[6], acc[7]);
    pk.x = *(uint32_t*)&b01; pk.y = *(uint32_t*)&b23;
    pk.z = *(uint32_t*)&b45; pk.w = *(uint32_t*)&b67;
    *(uint4*)(g_zb + ng * HF + c) = pk;
}

// ================= semantic GEMM (bf16, cp.async, tanh.approx) ===================
__global__ __launch_bounds__(256) void sem_mma_k(const float* __restrict__ b1,
                                                 const float* __restrict__ w2) {
    __shared__ __align__(16) char sA[2][16384];
    __shared__ __align__(16) char sB[2][16384];
    __shared__ float s_b1[HID], s_w2[HID], s_acc[NP];
    const int tid = threadIdx.x;
    const int wid = tid >> 5, lane = tid & 31;
    const int wm = wid & 3, wn = wid >> 2;
    const int row0 = blockIdx.x * 128;

    if (tid < NP) s_acc[tid] = 0.f;
    if (tid < HID) { s_b1[tid] = b1[tid]; s_w2[tid] = w2[tid]; }

    const char* Ag = (const char*)g_zb;
    const char* Bg = (const char*)g_w1t;

    float c[2][8][4];
    #pragma unroll
    for (int a = 0; a < 2; a++)
        #pragma unroll
        for (int b = 0; b < 8; b++)
            #pragma unroll
            for (int q = 0; q < 4; q++) c[a][b][q] = 0.f;

    const uint32_t sAb0 = smem_u32(sA[0]), sBb0 = smem_u32(sB[0]);

    auto load_tile = [&](int kc, int buf) {
        #pragma unroll
        for (int u = 0; u < 4; u++) {
            int i = tid + u * 256;
            int r = i >> 3, q = i & 7;
            uint32_t so = SWZ128((uint32_t)(r * 128 + q * 16));
            int gr = row0 + r;
            uint32_t sa = sAb0 + buf * 16384 + so;
            if (gr < NPN)
                CP_ASYNC16(sa, Ag + (size_t)gr * 512 + kc * 128 + q * 16);
            else
                *(uint4*)(sA[buf] + so) = make_uint4(0u, 0u, 0u, 0u);
            CP_ASYNC16(sBb0 + buf * 16384 + so, Bg + (size_t)r * 512 + kc * 128 + q * 16);
        }
    };

    load_tile(0, 0);
    CP_COMMIT();

    for (int kc = 0; kc < 4; kc++) {
        const int cur = kc & 1;
        if (kc + 1 < 4) {
            load_tile(kc + 1, cur ^ 1);
            CP_COMMIT();
            CP_WAIT(1);
        } else {
            CP_WAIT(0);
        }
        __syncthreads();
        const uint32_t sAb = sAb0 + cur * 16384;
        const uint32_t sBb = sBb0 + cur * 16384;
        #pragma unroll
        for (int ks = 0; ks < 4; ks++) {
            const int k0 = ks * 16;
            uint32_t a[2][4], b[4][4];
            #pragma unroll
            for (int fm = 0; fm < 2; fm++) {
                int row = wm * 32 + fm * 16 + ((lane >> 3) & 1) * 8 + (lane & 7);
                int kcol = k0 + (lane >> 4) * 8;
                ldsm_x4(a[fm][0], a[fm][1], a[fm][2], a[fm][3],
                        sAb + SWZ128((uint32_t)(row * 128 + kcol * 2)));
            }
            #pragma unroll
            for (int fp = 0; fp < 4; fp++) {
                int nrow = wn * 64 + fp * 16 + (lane >> 4) * 8 + (lane & 7);
                int kcol = k0 + ((lane >> 3) & 1) * 8;
                ldsm_x4(b[fp][0], b[fp][1], b[fp][2], b[fp][3],
                        sBb + SWZ128((uint32_t)(nrow * 128 + kcol * 2)));
            }
            #pragma unroll
            for (int fm = 0; fm < 2; fm++)
                #pragma unroll
                for (int fn = 0; fn < 8; fn++)
                    mma_bf16(c[fm][fn], a[fm], b[fn >> 1][(fn & 1) * 2], b[fn >> 1][(fn & 1) * 2 + 1]);
        }
        __syncthreads();
    }

    #pragma unroll
    for (int fm = 0; fm < 2; fm++) {
        int rbase = row0 + wm * 32 + fm * 16 + (lane >> 2);
        #pragma unroll
        for (int half = 0; half < 2; half++) {
            int grow = rbase + half * 8;
            float v = 0.f;
            #pragma unroll
            for (int fn = 0; fn < 8; fn++) {
                int col = wn * 64 + fn * 8 + (lane & 3) * 2;
                v += tanh_fast(c[fm][fn][half * 2]     + s_b1[col])     * s_w2[col];
                v += tanh_fast(c[fm][fn][half * 2 + 1] + s_b1[col + 1]) * s_w2[col + 1];
            }
            v += __shfl_xor_sync(0xffffffffu, v, 1);
            v += __shfl_xor_sync(0xffffffffu, v, 2);
            if ((lane & 3) == 0 && grow < NPN)
                atomicAdd(&s_acc[grow / N_NODES], v);
        }
    }
    __syncthreads();
    if (tid < NP) atomicAdd(&g_wsum[tid], s_acc[tid]);
}

// ================= final combine =================
__global__ void final_k(float* __restrict__ out) {
    int idx = blockIdx.x * blockDim.x + threadIdx.x;
    if (idx >= N_NODES * (HF / 4)) return;
    float m0 = g_wsum[0] * (1.f / N_NODES);
    float m1 = g_wsum[1] * (1.f / N_NODES);
    float m2 = g_wsum[2] * (1.f / N_NODES);
    float mm = fmaxf(m0, fmaxf(m1, m2));
    float e0 = __expf(m0 - mm), e1 = __expf(m1 - mm), e2 = __expf(m2 - mm);
    float inv = 1.f / (e0 + e1 + e2);
    float b0 = e0 * inv, b1 = e1 * inv, b2 = e2 * inv;
    size_t off = (size_t)idx * 4;
    float4 z0 = *(const float4*)(g_z + off);
    float4 z1 = *(const float4*)(g_z + (size_t)N_NODES * HF + off);
    float4 z2 = *(const float4*)(g_z + (size_t)2 * N_NODES * HF + off);
    float4 o;
    o.x = b0 * z0.x + b1 * z1.x + b2 * z2.x;
    o.y = b0 * z0.y + b1 * z1.y + b2 * z2.y;
    o.z = b0 * z0.z + b1 * z1.z + b2 * z2.z;
    o.w = b0 * z0.w + b1 * z1.w + b2 * z2.w;
    *(float4*)(out + off) = o;
}

// ================= launch =================
extern "C" void kernel_launch(void* const* d_in, const int* in_sizes, int n_in,
                              void* d_out, int out_size) {
    const float* h        = (const float*)d_in[0];
    const int* e0         = (const int*)d_in[1];
    const int* e1         = (const int*)d_in[2];
    const int* e2         = (const int*)d_in[3];
    const float* gat_W    = (const float*)d_in[4];
    const float* att_src  = (const float*)d_in[5];
    const float* att_dst  = (const float*)d_in[6];
    const float* gat_bias = (const float*)d_in[7];
    const float* sa_w1    = (const float*)d_in[8];
    const float* sa_b1    = (const float*)d_in[9];
    const float* sa_w2    = (const float*)d_in[10];
    float* out = (float*)d_out;

    static bool init_done = false;
    static void* cnt_ptr = nullptr;
    static void* wsum_ptr = nullptr;
    static cudaStream_t s2 = nullptr;
    static cudaEvent_t evF = nullptr, evJ = nullptr;
    if (!init_done) {
        cudaFuncSetAttribute(gemm_mma_k, cudaFuncAttributeMaxDynamicSharedMemorySize, GSMEM);
        cudaGetSymbolAddress(&cnt_ptr, g_cnt);
        cudaGetSymbolAddress(&wsum_ptr, g_wsum);
        cudaStreamCreateWithFlags(&s2, cudaStreamNonBlocking);
        cudaEventCreateWithFlags(&evF, cudaEventDisableTiming);
        cudaEventCreateWithFlags(&evJ, cudaEventDisableTiming);
        init_done = true;
    }

    // fork: CSR setup on s2, concurrent with conv + GEMM chain on default stream
    cudaEventRecord(evF, 0);
    cudaStreamWaitEvent(s2, evF, 0);
    cudaMemsetAsync(cnt_ptr, 0, NPN * sizeof(int), s2);
    hist_k<<<(NP * E_EDGES + 255) / 256, 256, 0, s2>>>(e0, e1, e2);
    scan_k<<<1, 1024, 0, s2>>>();
    scatter_k<<<(NP * E_EDGES + 255) / 256, 256, 0, s2>>>(e0, e1, e2);
    cudaEventRecord(evJ, s2);

    // main chain
    cudaMemsetAsync(wsum_ptr, 0, NP * sizeof(float));
    conv_h_k<<<(N_NODES * DIN + 255) / 256, 256>>>(h);
    dim3 tgrid(8, 8, NP + 1);
    transpose_k<<<tgrid, dim3(32, 32)>>>(gat_W, sa_w1);

    dim3 ggrid((N_NODES + 127) / 128, 1, NP);
    gemm_mma_k<<<ggrid, 512, GSMEM>>>(att_src, att_dst);

    edge_sum_k<<<(NP * E_EDGES + 255) / 256, 256>>>(e0, e1, e2);

    // join: agg needs CSR
    cudaStreamWaitEvent(0, evJ, 0);

    dim3 agrid((N_NODES + 7) / 8, NP);
    agg_k<<<agrid, 256>>>(gat_bias);

    sem_mma_k<<<(NPN + 127) / 128, 256>>>(sa_b1, sa_w2);

    final_k<<<(N_NODES * (HF / 4) + 255) / 256, 256>>>(out);
}